// round 1
// baseline (speedup 1.0000x reference)
#include <cuda_runtime.h>

#define HID 768
#define TPB 192          // 192 threads * float4 = 768
#define NWARP (TPB / 32)
#define LN_EPS 1e-12f

__device__ __forceinline__ float block_reduce_sum(float v, float* sh, int tid) {
    // warp reduce
    #pragma unroll
    for (int off = 16; off >= 1; off >>= 1)
        v += __shfl_down_sync(0xffffffffu, v, off);
    if ((tid & 31) == 0) sh[tid >> 5] = v;
    __syncthreads();
    float total = 0.f;
    #pragma unroll
    for (int w = 0; w < NWARP; w++) total += sh[w];
    return total;
}

__global__ void __launch_bounds__(TPB) bert_emb_ln_kernel(
    const int*   __restrict__ word_ids,
    const int*   __restrict__ modal_ids,
    const int*   __restrict__ seg_ids,
    const int*   __restrict__ npi_ids,
    const int*   __restrict__ posi_ids,
    const float* __restrict__ age_tau,
    const float* __restrict__ delay_tau,
    const float* __restrict__ word_t,
    const float* __restrict__ modal_t,
    const float* __restrict__ seg_t,
    const float* __restrict__ npi_t,
    const float* __restrict__ posi_t,
    const float* __restrict__ age_w,   // [H-1]
    const float* __restrict__ age_b,   // [H-1]
    const float* __restrict__ age_w0,  // [1]
    const float* __restrict__ age_b0,  // [1]
    const float* __restrict__ del_w,
    const float* __restrict__ del_b,
    const float* __restrict__ del_w0,
    const float* __restrict__ del_b0,
    const float* __restrict__ gamma,
    const float* __restrict__ beta,
    float*       __restrict__ out)
{
    __shared__ float sh[NWARP];

    const int tok = blockIdx.x;
    const int tid = threadIdx.x;
    const int h0  = tid * 4;

    // token scalars
    const int wi = word_ids[tok];
    const int mi = modal_ids[tok];
    const int si = seg_ids[tok];
    const int ni = npi_ids[tok];
    const int pi = posi_ids[tok];
    const float atau = age_tau[tok];
    const float dtau = delay_tau[tok];
    const float aw0 = __ldg(age_w0), ab0 = __ldg(age_b0);
    const float dw0 = __ldg(del_w0), db0 = __ldg(del_b0);

    // coalesced float4 gathers (row stride 768*4B = 3072B, 16B aligned)
    const float4* wrow = (const float4*)(word_t  + (long long)wi * HID);
    const float4* mrow = (const float4*)(modal_t + (long long)mi * HID);
    const float4* srow = (const float4*)(seg_t   + (long long)si * HID);
    const float4* nrow = (const float4*)(npi_t   + (long long)ni * HID);
    const float4* prow = (const float4*)(posi_t  + (long long)pi * HID);

    float4 wv = wrow[tid];
    float4 mv = mrow[tid];
    float4 sv = srow[tid];
    float4 nv = nrow[tid];
    float4 pv = prow[tid];

    float x[4];
    x[0] = wv.x + mv.x + sv.x + nv.x + pv.x;
    x[1] = wv.y + mv.y + sv.y + nv.y + pv.y;
    x[2] = wv.z + mv.z + sv.z + nv.z + pv.z;
    x[3] = wv.w + mv.w + sv.w + nv.w + pv.w;

    // time2vec for age and delay (last hidden index uses the linear term)
    #pragma unroll
    for (int i = 0; i < 4; i++) {
        int h = h0 + i;
        float av, dv;
        if (h < HID - 1) {
            av = sinf(fmaf(atau, __ldg(age_w + h), __ldg(age_b + h)));
            dv = sinf(fmaf(dtau, __ldg(del_w + h), __ldg(del_b + h)));
        } else {
            av = fmaf(atau, aw0, ab0);
            dv = fmaf(dtau, dw0, db0);
        }
        x[i] += av + dv;
    }

    // ---- LayerNorm: two-pass (mean, then mean((x-mu)^2)), matching reference
    float s = x[0] + x[1] + x[2] + x[3];
    float total = block_reduce_sum(s, sh, tid);
    float mu = total * (1.0f / HID);
    __syncthreads();  // protect sh[] reuse

    float d0 = x[0] - mu, d1 = x[1] - mu, d2 = x[2] - mu, d3 = x[3] - mu;
    float sq = d0 * d0 + d1 * d1 + d2 * d2 + d3 * d3;
    float vtot = block_reduce_sum(sq, sh, tid);
    float rstd = rsqrtf(vtot * (1.0f / HID) + LN_EPS);

    const float4 g4 = ((const float4*)gamma)[tid];
    const float4 b4 = ((const float4*)beta)[tid];

    float4 o;
    o.x = fmaf(d0 * rstd, g4.x, b4.x);
    o.y = fmaf(d1 * rstd, g4.y, b4.y);
    o.z = fmaf(d2 * rstd, g4.z, b4.z);
    o.w = fmaf(d3 * rstd, g4.w, b4.w);
    ((float4*)out)[(long long)tok * TPB + tid] = o;
}

extern "C" void kernel_launch(void* const* d_in, const int* in_sizes, int n_in,
                              void* d_out, int out_size) {
    const int*   word_ids  = (const int*)  d_in[0];
    const int*   modal_ids = (const int*)  d_in[1];
    const int*   seg_ids   = (const int*)  d_in[2];
    const int*   npi_ids   = (const int*)  d_in[3];
    const int*   posi_ids  = (const int*)  d_in[4];
    const float* age_tau   = (const float*)d_in[5];
    const float* delay_tau = (const float*)d_in[6];
    const float* word_t    = (const float*)d_in[7];
    const float* modal_t   = (const float*)d_in[8];
    const float* seg_t     = (const float*)d_in[9];
    const float* npi_t     = (const float*)d_in[10];
    const float* posi_t    = (const float*)d_in[11];
    const float* age_w     = (const float*)d_in[12];
    const float* age_b     = (const float*)d_in[13];
    const float* age_w0    = (const float*)d_in[14];
    const float* age_b0    = (const float*)d_in[15];
    const float* del_w     = (const float*)d_in[16];
    const float* del_b     = (const float*)d_in[17];
    const float* del_w0    = (const float*)d_in[18];
    const float* del_b0    = (const float*)d_in[19];
    const float* gamma     = (const float*)d_in[20];
    const float* beta      = (const float*)d_in[21];
    float* out = (float*)d_out;

    const int n_tokens = in_sizes[0];  // B*S = 16384
    bert_emb_ln_kernel<<<n_tokens, TPB>>>(
        word_ids, modal_ids, seg_ids, npi_ids, posi_ids,
        age_tau, delay_tau,
        word_t, modal_t, seg_t, npi_t, posi_t,
        age_w, age_b, age_w0, age_b0,
        del_w, del_b, del_w0, del_b0,
        gamma, beta, out);
}

// round 2
// speedup vs baseline: 1.3813x; 1.3813x over previous
#include <cuda_runtime.h>

#define HID 768
#define TPB 192          // 192 threads * float4 = 768
#define NWARP (TPB / 32)
#define LN_EPS 1e-12f

__device__ __forceinline__ float block_reduce_sum(float v, float* sh, int tid) {
    #pragma unroll
    for (int off = 16; off >= 1; off >>= 1)
        v += __shfl_down_sync(0xffffffffu, v, off);
    if ((tid & 31) == 0) sh[tid >> 5] = v;
    __syncthreads();
    float total = 0.f;
    #pragma unroll
    for (int w = 0; w < NWARP; w++) total += sh[w];
    return total;
}

__global__ void __launch_bounds__(TPB) bert_emb_ln_kernel(
    const int*   __restrict__ word_ids,
    const int*   __restrict__ modal_ids,
    const int*   __restrict__ seg_ids,
    const int*   __restrict__ npi_ids,
    const int*   __restrict__ posi_ids,
    const float* __restrict__ age_tau,
    const float* __restrict__ delay_tau,
    const float* __restrict__ word_t,
    const float* __restrict__ modal_t,
    const float* __restrict__ seg_t,
    const float* __restrict__ npi_t,
    const float* __restrict__ posi_t,
    const float* __restrict__ age_w,   // [H-1]
    const float* __restrict__ age_b,   // [H-1]
    const float* __restrict__ age_w0,  // [1]
    const float* __restrict__ age_b0,  // [1]
    const float* __restrict__ del_w,
    const float* __restrict__ del_b,
    const float* __restrict__ del_w0,
    const float* __restrict__ del_b0,
    const float* __restrict__ gamma,
    const float* __restrict__ beta,
    float*       __restrict__ out)
{
    __shared__ float sh[NWARP];

    const int tok = blockIdx.x;
    const int tid = threadIdx.x;

    // token scalars
    const int wi = word_ids[tok];
    const int mi = modal_ids[tok];
    const int si = seg_ids[tok];
    const int ni = npi_ids[tok];
    const int pi = posi_ids[tok];
    const float atau = age_tau[tok];
    const float dtau = delay_tau[tok];

    // coalesced float4 gathers (row stride 768*4B = 3072B, 16B aligned)
    const float4 wv = ((const float4*)(word_t  + (long long)wi * HID))[tid];
    const float4 mv = ((const float4*)(modal_t + (long long)mi * HID))[tid];
    const float4 sv = ((const float4*)(seg_t   + (long long)si * HID))[tid];
    const float4 nv = ((const float4*)(npi_t   + (long long)ni * HID))[tid];
    const float4 pv = ((const float4*)(posi_t  + (long long)pi * HID))[tid];

    float x[4];
    x[0] = wv.x + mv.x + sv.x + nv.x + pv.x;
    x[1] = wv.y + mv.y + sv.y + nv.y + pv.y;
    x[2] = wv.z + mv.z + sv.z + nv.z + pv.z;
    x[3] = wv.w + mv.w + sv.w + nv.w + pv.w;

    // ---- time2vec (age + delay). Weight arrays are H-1=767 long, so the
    // last thread (h = 764..767) takes a scalar path; all others do aligned
    // float4 loads of w/b for both age and delay.
    if (tid < TPB - 1) {
        const float4 aw = __ldg((const float4*)age_w + tid);
        const float4 ab = __ldg((const float4*)age_b + tid);
        const float4 dw = __ldg((const float4*)del_w + tid);
        const float4 db = __ldg((const float4*)del_b + tid);
        x[0] += __sinf(fmaf(atau, aw.x, ab.x)) + __sinf(fmaf(dtau, dw.x, db.x));
        x[1] += __sinf(fmaf(atau, aw.y, ab.y)) + __sinf(fmaf(dtau, dw.y, db.y));
        x[2] += __sinf(fmaf(atau, aw.z, ab.z)) + __sinf(fmaf(dtau, dw.z, db.z));
        x[3] += __sinf(fmaf(atau, aw.w, ab.w)) + __sinf(fmaf(dtau, dw.w, db.w));
    } else {
        const int h0 = tid * 4;  // 764
        #pragma unroll
        for (int i = 0; i < 3; i++) {
            x[i] += __sinf(fmaf(atau, __ldg(age_w + h0 + i), __ldg(age_b + h0 + i)))
                  + __sinf(fmaf(dtau, __ldg(del_w + h0 + i), __ldg(del_b + h0 + i)));
        }
        x[3] += fmaf(atau, __ldg(age_w0), __ldg(age_b0))
              + fmaf(dtau, __ldg(del_w0), __ldg(del_b0));
    }

    // ---- LayerNorm: two-pass (mean, then mean((x-mu)^2)), matching reference
    float s = x[0] + x[1] + x[2] + x[3];
    float total = block_reduce_sum(s, sh, tid);
    float mu = total * (1.0f / HID);
    __syncthreads();  // protect sh[] reuse

    float d0 = x[0] - mu, d1 = x[1] - mu, d2 = x[2] - mu, d3 = x[3] - mu;
    float sq = d0 * d0 + d1 * d1 + d2 * d2 + d3 * d3;
    float vtot = block_reduce_sum(sq, sh, tid);
    float rstd = rsqrtf(vtot * (1.0f / HID) + LN_EPS);

    const float4 g4 = __ldg((const float4*)gamma + tid);
    const float4 b4 = __ldg((const float4*)beta + tid);

    float4 o;
    o.x = fmaf(d0 * rstd, g4.x, b4.x);
    o.y = fmaf(d1 * rstd, g4.y, b4.y);
    o.z = fmaf(d2 * rstd, g4.z, b4.z);
    o.w = fmaf(d3 * rstd, g4.w, b4.w);
    ((float4*)out)[(long long)tok * TPB + tid] = o;
}

extern "C" void kernel_launch(void* const* d_in, const int* in_sizes, int n_in,
                              void* d_out, int out_size) {
    const int*   word_ids  = (const int*)  d_in[0];
    const int*   modal_ids = (const int*)  d_in[1];
    const int*   seg_ids   = (const int*)  d_in[2];
    const int*   npi_ids   = (const int*)  d_in[3];
    const int*   posi_ids  = (const int*)  d_in[4];
    const float* age_tau   = (const float*)d_in[5];
    const float* delay_tau = (const float*)d_in[6];
    const float* word_t    = (const float*)d_in[7];
    const float* modal_t   = (const float*)d_in[8];
    const float* seg_t     = (const float*)d_in[9];
    const float* npi_t     = (const float*)d_in[10];
    const float* posi_t    = (const float*)d_in[11];
    const float* age_w     = (const float*)d_in[12];
    const float* age_b     = (const float*)d_in[13];
    const float* age_w0    = (const float*)d_in[14];
    const float* age_b0    = (const float*)d_in[15];
    const float* del_w     = (const float*)d_in[16];
    const float* del_b     = (const float*)d_in[17];
    const float* del_w0    = (const float*)d_in[18];
    const float* del_b0    = (const float*)d_in[19];
    const float* gamma     = (const float*)d_in[20];
    const float* beta      = (const float*)d_in[21];
    float* out = (float*)d_out;

    const int n_tokens = in_sizes[0];  // B*S = 16384
    bert_emb_ln_kernel<<<n_tokens, TPB>>>(
        word_ids, modal_ids, seg_ids, npi_ids, posi_ids,
        age_tau, delay_tau,
        word_t, modal_t, seg_t, npi_t, posi_t,
        age_w, age_b, age_w0, age_b0,
        del_w, del_b, del_w0, del_b0,
        gamma, beta, out);
}